// round 16
// speedup vs baseline: 7.6900x; 1.0309x over previous
#include <cuda_runtime.h>
#include <cuda_bf16.h>
#include <cuda_fp8.h>
#include <math.h>

typedef __nv_bfloat16 bf16;

#define DIMN   1024
#define NHEAD  16
#define HDIM   64
#define SEQL   2048
#define BATCH  2
#define TOK    4096
#define HIDDEN 2816

// ---------------- scratch ----------------
__device__ float d_t [BATCH*512];
__device__ float d_tp[BATCH*512*8];
__device__ float d_f0[TOK*DIMN];

__device__ bf16 b_wq[DIMN*DIMN], b_wk[DIMN*DIMN], b_wv[DIMN*DIMN], b_wo[DIMN*DIMN];
__device__ unsigned char b_w13t[(size_t)2*HIDDEN*DIMN];   // fp8 [N][K] w1|w3, x256
__device__ unsigned char b_w2t[(size_t)DIMN*HIDDEN];      // fp8 [N][K], x64
__device__ bf16 b_xp[BATCH*8192*256];
__device__ bf16 b_gm[BATCH*256*256];
__device__ bf16 b_gf[BATCH*256*256];
__device__ bf16 b_xa[TOK*DIMN];
__device__ unsigned char b_xm8[TOK*DIMN];                 // fp8 xm, x16
__device__ bf16 b_q [TOK*DIMN], b_k[TOK*DIMN], b_v[TOK*DIMN], b_ao[TOK*DIMN];
__device__ unsigned char b_h8[(size_t)TOK*HIDDEN];        // fp8 gated h, x256

// ---------------- helpers ----------------
__device__ __forceinline__ float blockSum256(float v) {
    __shared__ float red[8];
    int lane = threadIdx.x & 31, wid = threadIdx.x >> 5;
    #pragma unroll
    for (int o = 16; o > 0; o >>= 1) v += __shfl_xor_sync(0xffffffffu, v, o);
    __syncthreads();
    if (lane == 0) red[wid] = v;
    __syncthreads();
    float s = red[0];
    #pragma unroll
    for (int w = 1; w < 8; w++) s += red[w];
    return s;
}
__device__ __forceinline__ void mma16(float* c, unsigned a0, unsigned a1, unsigned a2, unsigned a3,
                                      unsigned b0, unsigned b1) {
    asm volatile("mma.sync.aligned.m16n8k16.row.col.f32.bf16.bf16.f32 "
        "{%0,%1,%2,%3}, {%4,%5,%6,%7}, {%8,%9}, {%0,%1,%2,%3};"
        : "+f"(c[0]), "+f"(c[1]), "+f"(c[2]), "+f"(c[3])
        : "r"(a0), "r"(a1), "r"(a2), "r"(a3), "r"(b0), "r"(b1));
}
__device__ __forceinline__ void mma8f8(float* c, unsigned a0, unsigned a1, unsigned a2, unsigned a3,
                                       unsigned b0, unsigned b1) {
    asm volatile("mma.sync.aligned.m16n8k32.row.col.f32.e4m3.e4m3.f32 "
        "{%0,%1,%2,%3}, {%4,%5,%6,%7}, {%8,%9}, {%0,%1,%2,%3};"
        : "+f"(c[0]), "+f"(c[1]), "+f"(c[2]), "+f"(c[3])
        : "r"(a0), "r"(a1), "r"(a2), "r"(a3), "r"(b0), "r"(b1));
}
__device__ __forceinline__ void ldmx4(unsigned& r0, unsigned& r1, unsigned& r2, unsigned& r3, unsigned a) {
    asm volatile("ldmatrix.sync.aligned.m8n8.x4.shared.b16 {%0,%1,%2,%3}, [%4];"
                 : "=r"(r0), "=r"(r1), "=r"(r2), "=r"(r3) : "r"(a));
}
__device__ __forceinline__ void ldmx4t(unsigned& r0, unsigned& r1, unsigned& r2, unsigned& r3, unsigned a) {
    asm volatile("ldmatrix.sync.aligned.m8n8.x4.trans.shared.b16 {%0,%1,%2,%3}, [%4];"
                 : "=r"(r0), "=r"(r1), "=r"(r2), "=r"(r3) : "r"(a));
}
__device__ __forceinline__ void cpa16(unsigned s, const void* g) {
    asm volatile("cp.async.cg.shared.global [%0], [%1], 16;" :: "r"(s), "l"(g));
}
__device__ __forceinline__ unsigned pack_bf(float a, float b) {
    __nv_bfloat162 t; t.x = __float2bfloat16_rn(a); t.y = __float2bfloat16_rn(b);
    return *(unsigned*)&t;
}
__device__ __forceinline__ float2 unpack_bf(unsigned u) {
    __nv_bfloat162 t = *(__nv_bfloat162*)&u;
    return make_float2(__bfloat162float(t.x), __bfloat162float(t.y));
}
__device__ __forceinline__ unsigned short pack_f8(float lo, float hi) {
    unsigned short r;
    asm("cvt.rn.satfinite.e4m3x2.f32 %0, %1, %2;" : "=h"(r) : "f"(hi), "f"(lo));
    return r;
}

// ---------------- weight conversions (4 bf16 weights) ----------------
__global__ void cvt_all(const float* __restrict__ s0, const float* __restrict__ s1,
                        const float* __restrict__ s2, const float* __restrict__ s3) {
    int w = blockIdx.y;
    const float* src = (w == 0) ? s0 : (w == 1 ? s1 : (w == 2 ? s2 : s3));
    bf16* dst = (w == 0) ? b_wq : (w == 1 ? b_wk : (w == 2 ? b_wv : b_wo));
    int i = (blockIdx.x * 256 + threadIdx.x) * 16;
    float4 a = *(const float4*)(src + i);
    float4 b = *(const float4*)(src + i + 4);
    float4 c = *(const float4*)(src + i + 8);
    float4 d = *(const float4*)(src + i + 12);
    uint4 o1, o2;
    o1.x = pack_bf(a.x, a.y); o1.y = pack_bf(a.z, a.w);
    o1.z = pack_bf(b.x, b.y); o1.w = pack_bf(b.z, b.w);
    o2.x = pack_bf(c.x, c.y); o2.y = pack_bf(c.z, c.w);
    o2.z = pack_bf(d.x, d.y); o2.w = pack_bf(d.z, d.w);
    *(uint4*)(dst + i) = o1;
    *(uint4*)(dst + i + 8) = o2;
}

// ---- w1/w3 [K=1024][N=2816] fp32 -> w13t [N][K] e4m3 x256 ----
__global__ void cvt_w13t(const float* __restrict__ s1, const float* __restrict__ s3) {
    const float* src = blockIdx.y ? s3 : s1;
    unsigned char* dst = b_w13t + (blockIdx.y ? (size_t)HIDDEN*DIMN : 0);
    const int ntN = HIDDEN / 32;
    int kt = blockIdx.x / ntN, nt = blockIdx.x % ntN;
    __shared__ float sT[32][33];
    int tx = threadIdx.x & 31, ty0 = threadIdx.x >> 5;
    #pragma unroll
    for (int it = 0; it < 4; it++)
        sT[ty0 + 8*it][tx] = src[(size_t)(kt*32 + ty0 + 8*it) * HIDDEN + nt*32 + tx];
    __syncthreads();
    #pragma unroll
    for (int it = 0; it < 4; it++) {
        int row = ty0 + 8*it;
        __nv_fp8_e4m3 v(sT[tx][row] * 256.f);
        dst[(size_t)(nt*32 + row) * DIMN + kt*32 + tx] = *(unsigned char*)&v;
    }
}

// ---- w2 [K=2816][N=1024] fp32 -> w2t [N][K] e4m3 x64 ----
__global__ void cvt_w2t(const float* __restrict__ src) {
    int kt = blockIdx.x >> 5, nt = blockIdx.x & 31;
    __shared__ float sT[32][33];
    int tx = threadIdx.x & 31, ty0 = threadIdx.x >> 5;
    #pragma unroll
    for (int it = 0; it < 4; it++)
        sT[ty0 + 8*it][tx] = src[(size_t)(kt*32 + ty0 + 8*it) * DIMN + nt*32 + tx];
    __syncthreads();
    #pragma unroll
    for (int it = 0; it < 4; it++) {
        int row = ty0 + 8*it;
        __nv_fp8_e4m3 v(sT[tx][row] * 64.f);
        b_w2t[(size_t)(nt*32 + row) * HIDDEN + kt*32 + tx] = *(unsigned char*)&v;
    }
}

// -------- proj_t split-K: part grid (BATCH, 16, 8); red grid (4) --------
__global__ void proj_t_part(const float* __restrict__ ad, const float* __restrict__ pw,
                            float* __restrict__ tp) {
    int b = blockIdx.x, o0 = blockIdx.y * 32, z = blockIdx.z;   // i in [z*128, z*128+128)
    __shared__ float s[128];
    __shared__ float red[8][32];
    int tid = threadIdx.x;
    if (tid < 128) {
        float zz = ad[b*DIMN + z*128 + tid];
        s[tid] = zz / (1.f + expf(-zz));
    }
    __syncthreads();
    int warp = tid >> 5, lane = tid & 31;
    const float* pwc = pw + (size_t)(z*128)*512 + o0 + lane;
    float acc = 0.f;
    #pragma unroll
    for (int i = warp*16; i < warp*16 + 16; i++)
        acc += s[i] * pwc[(size_t)i*512];
    red[warp][lane] = acc;
    __syncthreads();
    if (tid < 32)
        tp[((size_t)(b*512 + o0 + tid))*8 + z]
            = red[0][tid] + red[1][tid] + red[2][tid] + red[3][tid]
            + red[4][tid] + red[5][tid] + red[6][tid] + red[7][tid];
}

__global__ void proj_t_red(const float* __restrict__ tp, const float* __restrict__ pb,
                           float* __restrict__ t) {
    int idx = blockIdx.x * 256 + threadIdx.x;    // 1024 total
    int o = idx & 511;
    const float* p = tp + (size_t)idx * 8;
    float r = pb[o];
    #pragma unroll
    for (int z = 0; z < 8; z++) r += p[z];
    t[idx] = r;
}

// grid (4, 32): block covers 8 q-rows
__global__ void make_g_kernel(const float* __restrict__ t) {
    int b = blockIdx.x >> 1, which = blockIdx.x & 1;
    int q0 = blockIdx.y * 8;
    const float* m = t + b*512 + which*256;
    __shared__ float cs[256], ms[256];
    __shared__ bf16 gd[512];
    int d = threadIdx.x;
    cs[d] = cosf((6.283185307179586f / 256.0f) * (float)d);
    ms[d] = m[d];
    __syncthreads();
    float acc = 0.f;
    #pragma unroll 4
    for (int k = 0; k < 256; k++) acc += ms[k] * cs[(k*d) & 255];
    bf16 gv = __float2bfloat16_rn(acc * (1.0f / 256.0f));
    gd[d] = gv; gd[d + 256] = gv;
    __syncthreads();
    bf16* Bg = (which ? b_gf : b_gm) + b * 65536;
    #pragma unroll
    for (int q = q0; q < q0 + 8; q++)
        Bg[q*256 + d] = gd[d - q + 256];
}

__global__ void patchify(const float* __restrict__ x) {
    int c = blockIdx.x * 256 + threadIdx.x;
    int q  = (c & 31) * 8;
    int pi = (c >> 5) & 8191;
    int b  = c >> 18;
    int p = q >> 4, qq = q & 15;
    const float* src = x + ((size_t)(b*2048 + (pi >> 6)*16 + p)) * DIMN + (pi & 63)*16 + qq;
    float4 a = *(const float4*)src;
    float4 v = *(const float4*)(src + 4);
    uint4 o;
    o.x = pack_bf(a.x, a.y); o.y = pack_bf(a.z, a.w);
    o.z = pack_bf(v.x, v.y); o.w = pack_bf(v.z, v.w);
    *(uint4*)(b_xp + (size_t)c * 8) = o;
}

// ================= bf16 GEMM core (4-stage cp.async) =================
#define AKE 40
#define BNE 264
#define A_ELT (128*AKE)
#define B_ELT (32*BNE)
#define STG_ELT (A_ELT + B_ELT)
#define GEMM_SMEM (4 * STG_ELT * 2)

#define GEMM_PROLOG(Aptr, Bptr, Kdim, Ndim, bmv, bnv)                                    \
    extern __shared__ bf16 smb[];                                                        \
    const unsigned sbase = (unsigned)__cvta_generic_to_shared(smb);                      \
    const int tid  = threadIdx.x;                                                        \
    const int lane = tid & 31;                                                           \
    const int warp = tid >> 5;                                                           \
    const int g    = lane >> 2;                                                          \
    const int t4   = lane & 3;                                                           \
    const int lm   = lane & 15;                                                          \
    const int lh   = lane >> 4;                                                          \
    const int wm = (warp >> 2) * 64;                                                     \
    const int wn = (warp & 3) * 64;                                                      \
    float acc[4][8][4];                                                                  \
    _Pragma("unroll") for (int i = 0; i < 4; i++)                                        \
        _Pragma("unroll") for (int j = 0; j < 8; j++)                                    \
            _Pragma("unroll") for (int r = 0; r < 4; r++) acc[i][j][r] = 0.f;            \
    const int ktiles = (Kdim) >> 5;                                                      \
    auto load_stage = [&](int st, int k0) {                                              \
        unsigned sa = sbase + (unsigned)(st * STG_ELT) * 2u;                             \
        unsigned sb = sa + A_ELT * 2u;                                                   \
        _Pragma("unroll") for (int u = 0; u < 2; u++) {                                  \
            int c = tid + 256*u;                                                         \
            int r = c >> 2, o = (c & 3) * 8;                                             \
            cpa16(sa + (unsigned)(r*AKE + o)*2u, (Aptr) + (size_t)((bmv) + r) * (Kdim) + k0 + o); \
        }                                                                                \
        _Pragma("unroll") for (int u = 0; u < 4; u++) {                                  \
            int c = tid + 256*u;                                                         \
            int r = c >> 5, o = (c & 31) * 8;                                            \
            cpa16(sb + (unsigned)(r*BNE + o)*2u, (Bptr) + (size_t)(k0 + r) * (Ndim) + (bnv) + o); \
        }                                                                                \
    };                                                                                   \
    load_stage(0, 0);                                                                    \
    asm volatile("cp.async.commit_group;");                                              \
    load_stage(1, 32);                                                                   \
    asm volatile("cp.async.commit_group;");                                              \
    load_stage(2, 64);                                                                   \
    asm volatile("cp.async.commit_group;");                                              \
    for (int t = 0; t < ktiles; t++) {                                                   \
        asm volatile("cp.async.wait_group 2;");                                          \
        __syncthreads();                                                                 \
        int nt = t + 3;                                                                  \
        if (nt < ktiles) load_stage(nt & 3, nt * 32);                                    \
        asm volatile("cp.async.commit_group;");                                          \
        unsigned sa = sbase + (unsigned)((t & 3) * STG_ELT) * 2u;                        \
        unsigned sb = sa + A_ELT * 2u;                                                   \
        _Pragma("unroll") for (int kk = 0; kk < 32; kk += 16) {                          \
            unsigned af[4][4], bfr[8][2];                                                \
            _Pragma("unroll") for (int i = 0; i < 4; i++)                                \
                ldmx4(af[i][0], af[i][1], af[i][2], af[i][3],                            \
                      sa + (unsigned)((wm + 16*i + lm)*AKE + kk + lh*8)*2u);             \
            _Pragma("unroll") for (int j2 = 0; j2 < 4; j2++)                             \
                ldmx4t(bfr[2*j2][0], bfr[2*j2][1], bfr[2*j2+1][0], bfr[2*j2+1][1],       \
                       sb + (unsigned)((kk + lm)*BNE + wn + 16*j2 + lh*8)*2u);           \
            _Pragma("unroll") for (int i = 0; i < 4; i++)                                \
                _Pragma("unroll") for (int j = 0; j < 8; j++)                            \
                    mma16(acc[i][j], af[i][0], af[i][1], af[i][2], af[i][3],             \
                          bfr[j][0], bfr[j][1]);                                         \
        }                                                                                \
    }

// ---- generic gemm, bf16 out ----
__global__ __launch_bounds__(256, 1) void gemm_bf16o(const bf16* __restrict__ A,
                                                     const bf16* __restrict__ B,
                                                     bf16* __restrict__ Cb,
                                                     int M, int N, int K) {
    const int bm = blockIdx.y * 128;
    const int bn = blockIdx.x * 256;
    GEMM_PROLOG(A, B, K, N, bm, bn)
    #pragma unroll
    for (int i = 0; i < 4; i++) {
        int row0 = bm + wm + 16*i + g;
        #pragma unroll
        for (int j = 0; j < 8; j++) {
            int col = bn + wn + 8*j + 2*t4;
            *(unsigned*)(Cb + (size_t)row0 * N + col)       = pack_bf(acc[i][j][0], acc[i][j][1]);
            *(unsigned*)(Cb + (size_t)(row0 + 8) * N + col) = pack_bf(acc[i][j][2], acc[i][j][3]);
        }
    }
}

// ---- fused QKV gemm + RoPE + head-norm + sqk_eff ----
__global__ __launch_bounds__(256, 1) void gemm_qkv(const bf16* __restrict__ A,
                                                   const float* __restrict__ fcos,
                                                   const float* __restrict__ fsin,
                                                   const float* __restrict__ sqk) {
    const int wsel = blockIdx.x >> 2;
    const int bn = (blockIdx.x & 3) * 256;
    const int bm = blockIdx.y * 128;
    const bf16* B = (wsel == 0) ? b_wq : ((wsel == 1) ? b_wk : b_wv);
    bf16* C = (wsel == 0) ? b_q : ((wsel == 1) ? b_k : b_v);
    GEMM_PROLOG(A, B, DIMN, DIMN, bm, bn)
    if (wsel == 2) {
        #pragma unroll
        for (int i = 0; i < 4; i++) {
            int row0 = bm + wm + 16*i + g;
            #pragma unroll
            for (int j = 0; j < 8; j++) {
                int col = bn + wn + 8*j + 2*t4;
                *(unsigned*)(C + (size_t)row0 * DIMN + col)       = pack_bf(acc[i][j][0], acc[i][j][1]);
                *(unsigned*)(C + (size_t)(row0 + 8) * DIMN + col) = pack_bf(acc[i][j][2], acc[i][j][3]);
            }
        }
    } else {
        const int h = (bn + wn) >> 6;
        const float qscale = (wsel == 0) ? 8.f * 1.4426950408889634f : 1.f;
        #pragma unroll
        for (int i = 0; i < 4; i++) {
            int row0 = bm + wm + 16*i + g;
            int row1 = row0 + 8;
            float ss0 = 0.f, ss1 = 0.f;
            #pragma unroll
            for (int j = 0; j < 8; j++) {
                ss0 += acc[i][j][0]*acc[i][j][0] + acc[i][j][1]*acc[i][j][1];
                ss1 += acc[i][j][2]*acc[i][j][2] + acc[i][j][3]*acc[i][j][3];
            }
            ss0 += __shfl_xor_sync(0xffffffffu, ss0, 1);
            ss0 += __shfl_xor_sync(0xffffffffu, ss0, 2);
            ss1 += __shfl_xor_sync(0xffffffffu, ss1, 1);
            ss1 += __shfl_xor_sync(0xffffffffu, ss1, 2);
            float inv0 = qscale / fmaxf(sqrtf(ss0), 1e-12f);
            float inv1 = qscale / fmaxf(sqrtf(ss1), 1e-12f);
            int s0 = row0 & (SEQL - 1), s1 = row1 & (SEQL - 1);
            #pragma unroll
            for (int j = 0; j < 8; j++) {
                int pidx = 4*j + t4;
                int d = 8*j + 2*t4;
                float se0 = sqk[h*HDIM + d]     * 32.f;
                float se1 = sqk[h*HDIM + d + 1] * 32.f;
                float c0 = fcos[s0*32 + pidx], sn0 = fsin[s0*32 + pidx];
                float c1 = fcos[s1*32 + pidx], sn1 = fsin[s1*32 + pidx];
                float a0 = acc[i][j][0], a1 = acc[i][j][1];
                float b0 = acc[i][j][2], b1 = acc[i][j][3];
                int col = bn + wn + d;
                *(unsigned*)(C + (size_t)row0 * DIMN + col) =
                    pack_bf((a0*c0 - a1*sn0) * inv0 * se0, (a0*sn0 + a1*c0) * inv0 * se1);
                *(unsigned*)(C + (size_t)row1 * DIMN + col) =
                    pack_bf((b0*c1 - b1*sn1) * inv1 * se0, (b0*sn1 + b1*c1) * inv1 * se1);
            }
        }
    }
}

// ---- adafm gemm: Y = Xp @ Bg, scatter; bf16 out (attn) or fp8 x16 out (ffn) ----
__global__ __launch_bounds__(256, 1) void adafm_gemm(const bf16* __restrict__ Bg0,
                                                     bf16* __restrict__ Y,
                                                     unsigned char* __restrict__ Y8) {
    const int z  = blockIdx.z;
    const int bm = blockIdx.y * 128;
    const int bn = 0;
    const bf16* A = b_xp + (size_t)z * 8192 * 256;
    const bf16* B = Bg0 + (size_t)z * 65536;
    GEMM_PROLOG(A, B, 256, 256, bm, bn)
    #pragma unroll
    for (int i = 0; i < 4; i++) {
        int pi0 = bm + wm + 16*i + g;
        #pragma unroll
        for (int j = 0; j < 8; j++) {
            int col = wn + 8*j + 2*t4;
            int p = col >> 4, qq = col & 15;
            int pi1 = pi0 + 8;
            size_t off0 = (size_t)(z*2048 + (pi0 >> 6)*16 + p) * DIMN + (pi0 & 63)*16 + qq;
            size_t off1 = (size_t)(z*2048 + (pi1 >> 6)*16 + p) * DIMN + (pi1 & 63)*16 + qq;
            if (Y8) {
                *(unsigned short*)(Y8 + off0) = pack_f8(acc[i][j][0]*16.f, acc[i][j][1]*16.f);
                *(unsigned short*)(Y8 + off1) = pack_f8(acc[i][j][2]*16.f, acc[i][j][3]*16.f);
            } else {
                *(unsigned*)(Y + off0) = pack_bf(acc[i][j][0], acc[i][j][1]);
                *(unsigned*)(Y + off1) = pack_bf(acc[i][j][2], acc[i][j][3]);
            }
        }
    }
}

// ================= fp8 FFN w1/w3 GEMM + silu gate =================
#define F8AS 80
#define F8STG (128*F8AS + 256*F8AS)
#define FFN8_SMEM (4 * F8STG)

__global__ __launch_bounds__(256, 1) void gemm_ffn13f8(const float* __restrict__ su,
                                                       const float* __restrict__ sv) {
    const int bnb = blockIdx.x * 128;
    const int bm  = blockIdx.y * 128;
    extern __shared__ __align__(16) unsigned char sm8[];
    const unsigned sbase = (unsigned)__cvta_generic_to_shared(sm8);
    const int tid  = threadIdx.x;
    const int lane = tid & 31;
    const int warp = tid >> 5;
    const int g    = lane >> 2;
    const int t4   = lane & 3;
    const int lm   = lane & 15;
    const int lh   = lane >> 4;
    const int wm = (warp >> 2) * 64;
    const int wn = (warp & 3) * 32;
    const int q8 = lane >> 3, r8 = lane & 7;

    float acc1[4][4][4], acc3[4][4][4];
    #pragma unroll
    for (int i = 0; i < 4; i++)
        #pragma unroll
        for (int j = 0; j < 4; j++)
            #pragma unroll
            for (int r = 0; r < 4; r++) { acc1[i][j][r] = 0.f; acc3[i][j][r] = 0.f; }

    const int ktiles = DIMN >> 6;
    auto load_stage = [&](int st, int k0) {
        unsigned sa = sbase + (unsigned)(st * F8STG);
        unsigned sb = sa + 128*F8AS;
        #pragma unroll
        for (int u = 0; u < 2; u++) {
            int c = tid + 256*u;
            int r = c >> 2, o = (c & 3) * 16;
            cpa16(sa + (unsigned)(r*F8AS + o), b_xm8 + (size_t)(bm + r) * DIMN + k0 + o);
        }
        #pragma unroll
        for (int u = 0; u < 4; u++) {
            int c = tid + 256*u;
            int r = c >> 2, o = (c & 3) * 16;
            const unsigned char* src = (r < 128)
                ? (b_w13t + (size_t)(bnb + r) * DIMN)
                : (b_w13t + (size_t)HIDDEN*DIMN + (size_t)(bnb + r - 128) * DIMN);
            cpa16(sb + (unsigned)(r*F8AS + o), src + k0 + o);
        }
    };
    load_stage(0, 0);
    asm volatile("cp.async.commit_group;");
    load_stage(1, 64);
    asm volatile("cp.async.commit_group;");
    load_stage(2, 128);
    asm volatile("cp.async.commit_group;");

    for (int t = 0; t < ktiles; t++) {
        asm volatile("cp.async.wait_group 2;");
        __syncthreads();
        int nt = t + 3;
        if (nt < ktiles) load_stage(nt & 3, nt * 64);
        asm volatile("cp.async.commit_group;");
        unsigned sa = sbase + (unsigned)((t & 3) * F8STG);
        unsigned sb = sa + 128*F8AS;
        #pragma unroll
        for (int ks = 0; ks < 2; ks++) {
            int k0 = ks * 32;
            unsigned af[4][4], b1f[4][2], b3f[4][2];
            #pragma unroll
            for (int i = 0; i < 4; i++)
                ldmx4(af[i][0], af[i][1], af[i][2], af[i][3],
                      sa + (unsigned)((wm + 16*i + lm)*F8AS + k0 + lh*16));
            #pragma unroll
            for (int jp = 0; jp < 2; jp++) {
                int n0 = wn + 16*jp;
                unsigned ra = (unsigned)((n0 + ((q8 >> 1) << 3) + r8)*F8AS + k0 + ((q8 & 1) << 4));
                ldmx4(b1f[2*jp][0], b1f[2*jp][1], b1f[2*jp+1][0], b1f[2*jp+1][1], sb + ra);
                ldmx4(b3f[2*jp][0], b3f[2*jp][1], b3f[2*jp+1][0], b3f[2*jp+1][1],
                      sb + 128u*F8AS + ra);
            }
            #pragma unroll
            for (int i = 0; i < 4; i++)
                #pragma unroll
                for (int j = 0; j < 4; j++) {
                    mma8f8(acc1[i][j], af[i][0], af[i][1], af[i][2], af[i][3], b1f[j][0], b1f[j][1]);
                    mma8f8(acc3[i][j], af[i][0], af[i][1], af[i][2], af[i][3], b3f[j][0], b3f[j][1]);
                }
        }
    }

    const float SC = 53.06599664568481f;
    const float OS13 = 1.f / 4096.f;
    #pragma unroll
    for (int i = 0; i < 4; i++) {
        int row0 = bm + wm + 16*i + g;
        #pragma unroll
        for (int j = 0; j < 4; j++) {
            int col = bnb + wn + 8*j + 2*t4;
            float sv0 = sv[col] * SC * OS13, sv1 = sv[col+1] * SC * OS13;
            float su0 = su[col] * OS13,      su1 = su[col+1] * OS13;
            float z, sgl, outv[4];
            z = acc1[i][j][0] * sv0; sgl = z / (1.f + __expf(-z)); outv[0] = sgl * (acc3[i][j][0] * su0);
            z = acc1[i][j][1] * sv1; sgl = z / (1.f + __expf(-z)); outv[1] = sgl * (acc3[i][j][1] * su1);
            z = acc1[i][j][2] * sv0; sgl = z / (1.f + __expf(-z)); outv[2] = sgl * (acc3[i][j][2] * su0);
            z = acc1[i][j][3] * sv1; sgl = z / (1.f + __expf(-z)); outv[3] = sgl * (acc3[i][j][3] * su1);
            *(unsigned short*)(b_h8 + (size_t)row0 * HIDDEN + col)
                = pack_f8(outv[0]*256.f, outv[1]*256.f);
            *(unsigned short*)(b_h8 + (size_t)(row0 + 8) * HIDDEN + col)
                = pack_f8(outv[2]*256.f, outv[3]*256.f);
        }
    }
}

// ---- w2 fp8 GEMM: Cb bf16 = (h8/256) @ (w2t/64)^T ----
#define A8S 80
#define STG8 (128*A8S + 256*A8S)
#define W2F8_SMEM (4 * STG8)

__global__ __launch_bounds__(256, 1) void gemm_w2f8(bf16* __restrict__ Cb) {
    const int bm = blockIdx.y * 128;
    const int bn = blockIdx.x * 256;
    extern __shared__ __align__(16) unsigned char sm8[];
    const unsigned sbase = (unsigned)__cvta_generic_to_shared(sm8);
    const int tid  = threadIdx.x;
    const int lane = tid & 31;
    const int warp = tid >> 5;
    const int g    = lane >> 2;
    const int t4   = lane & 3;
    const int lm   = lane & 15;
    const int lh   = lane >> 4;
    const int wm = (warp >> 2) * 64;
    const int wn = (warp & 3) * 64;
    const int q8 = lane >> 3, r8 = lane & 7;

    float acc[4][8][4];
    #pragma unroll
    for (int i = 0; i < 4; i++)
        #pragma unroll
        for (int j = 0; j < 8; j++)
            #pragma unroll
            for (int r = 0; r < 4; r++) acc[i][j][r] = 0.f;

    const int ktiles = HIDDEN >> 6;
    auto load_stage = [&](int st, int k0) {
        unsigned sa = sbase + (unsigned)(st * STG8);
        unsigned sb = sa + 128*A8S;
        #pragma unroll
        for (int u = 0; u < 2; u++) {
            int c = tid + 256*u;
            int r = c >> 2, o = (c & 3) * 16;
            cpa16(sa + (unsigned)(r*A8S + o), b_h8 + (size_t)(bm + r) * HIDDEN + k0 + o);
        }
        #pragma unroll
        for (int u = 0; u < 4; u++) {
            int c = tid + 256*u;
            int r = c >> 2, o = (c & 3) * 16;
            cpa16(sb + (unsigned)(r*A8S + o), b_w2t + (size_t)(bn + r) * HIDDEN + k0 + o);
        }
    };
    load_stage(0, 0);
    asm volatile("cp.async.commit_group;");
    load_stage(1, 64);
    asm volatile("cp.async.commit_group;");
    load_stage(2, 128);
    asm volatile("cp.async.commit_group;");

    for (int t = 0; t < ktiles; t++) {
        asm volatile("cp.async.wait_group 2;");
        __syncthreads();
        int nt = t + 3;
        if (nt < ktiles) load_stage(nt & 3, nt * 64);
        asm volatile("cp.async.commit_group;");
        unsigned sa = sbase + (unsigned)((t & 3) * STG8);
        unsigned sb = sa + 128*A8S;
        #pragma unroll
        for (int ks = 0; ks < 2; ks++) {
            int k0 = ks * 32;
            unsigned af[4][4], bfr[8][2];
            #pragma unroll
            for (int i = 0; i < 4; i++)
                ldmx4(af[i][0], af[i][1], af[i][2], af[i][3],
                      sa + (unsigned)((wm + 16*i + lm)*A8S + k0 + lh*16));
            #pragma unroll
            for (int jp = 0; jp < 4; jp++) {
                int n0 = wn + 16*jp;
                unsigned addr = sb + (unsigned)((n0 + ((q8 >> 1) << 3) + r8)*A8S + k0 + ((q8 & 1) << 4));
                ldmx4(bfr[2*jp][0], bfr[2*jp][1], bfr[2*jp+1][0], bfr[2*jp+1][1], addr);
            }
            #pragma unroll
            for (int i = 0; i < 4; i++)
                #pragma unroll
                for (int j = 0; j < 8; j++)
                    mma8f8(acc[i][j], af[i][0], af[i][1], af[i][2], af[i][3],
                           bfr[j][0], bfr[j][1]);
        }
    }

    const float OS = 1.f / 16384.f;
    #pragma unroll
    for (int i = 0; i < 4; i++) {
        int row0 = bm + wm + 16*i + g;
        #pragma unroll
        for (int j = 0; j < 8; j++) {
            int col = bn + wn + 8*j + 2*t4;
            *(unsigned*)(Cb + (size_t)row0 * DIMN + col)       = pack_bf(acc[i][j][0]*OS, acc[i][j][1]*OS);
            *(unsigned*)(Cb + (size_t)(row0 + 8) * DIMN + col) = pack_bf(acc[i][j][2]*OS, acc[i][j][3]*OS);
        }
    }
}

// --------- FA2 flash attention, cp.async 3-stage ring ---------
#define FAE 72
#define FLASH_SMEM ((128 + 6*64) * FAE * 2)

__global__ __launch_bounds__(256, 2) void flash_attn(const bf16* __restrict__ Q,
                                                     const bf16* __restrict__ K,
                                                     const bf16* __restrict__ V,
                                                     bf16* __restrict__ O) {
    extern __shared__ bf16 fsm[];
    bf16* Qs = fsm;
    const unsigned sQ  = (unsigned)__cvta_generic_to_shared(Qs);
    const unsigned sK0 = sQ + 128*FAE*2u;
    const unsigned sV0 = sK0 + 3*64*FAE*2u;

    const int q0 = blockIdx.x * 128;
    const int h  = blockIdx.y;
    const int b  = blockIdx.z;
    const bf16* Qb = Q + (size_t)b*SEQL*DIMN + h*HDIM;
    const bf16* Kb = K + (size_t)b*SEQL*DIMN + h*HDIM;
    const bf16* Vb = V + (size_t)b*SEQL*DIMN + h*HDIM;
    bf16*       Ob = O + (size_t)b*SEQL*DIMN + h*HDIM;

    const int tid  = threadIdx.x;
    const int lane = tid & 31;
    const int warp = tid >> 5;
    const int g  = lane >> 2;
    const int t4 = lane & 3;
    const int lm = lane & 15;
    const int lh = lane >> 4;
    const int wm = warp * 16;

    auto loadKV = [&](int st, int k0) {
        unsigned sk = sK0 + (unsigned)st * 64*FAE*2u;
        unsigned sv = sV0 + (unsigned)st * 64*FAE*2u;
        #pragma unroll
        for (int u = 0; u < 2; u++) {
            int c = tid + 256*u;
            int r = c >> 3, ofs = (c & 7) * 8;
            cpa16(sk + (unsigned)(r*FAE + ofs)*2u, Kb + (size_t)(k0 + r)*DIMN + ofs);
            cpa16(sv + (unsigned)(r*FAE + ofs)*2u, Vb + (size_t)(k0 + r)*DIMN + ofs);
        }
    };

    #pragma unroll
    for (int u = 0; u < 4; u++) {
        int c = tid + 256*u;
        int r = c >> 3, ofs = (c & 7) * 8;
        *(uint4*)&Qs[r*FAE + ofs] = *(const uint4*)(Qb + (size_t)(q0 + r)*DIMN + ofs);
    }

    loadKV(0, 0);
    asm volatile("cp.async.commit_group;");
    loadKV(1, 64);
    asm volatile("cp.async.commit_group;");

    float o[8][4];
    #pragma unroll
    for (int j = 0; j < 8; j++)
        #pragma unroll
        for (int r = 0; r < 4; r++) o[j][r] = 0.f;
    float m0 = -1e30f, m1 = -1e30f, l0 = 0.f, l1 = 0.f;

    const int NT = SEQL / 64;
    for (int t = 0; t < NT; t++) {
        if (t + 1 < NT) asm volatile("cp.async.wait_group 1;");
        else            asm volatile("cp.async.wait_group 0;");
        __syncthreads();
        if (t + 2 < NT) {
            loadKV((t + 2) % 3, (t + 2) * 64);
            asm volatile("cp.async.commit_group;");
        }

        const unsigned sK = sK0 + (unsigned)(t % 3) * 64*FAE*2u;
        const unsigned sV = sV0 + (unsigned)(t % 3) * 64*FAE*2u;

        float s[8][4];
        #pragma unroll
        for (int j = 0; j < 8; j++)
            #pragma unroll
            for (int r = 0; r < 4; r++) s[j][r] = 0.f;

        #pragma unroll
        for (int kc = 0; kc < 4; kc++) {
            int kk = 16*kc;
            unsigned a0, a1, a2, a3;
            ldmx4(a0, a1, a2, a3, sQ + (unsigned)((wm + lm)*FAE + kk + lh*8)*2u);
            #pragma unroll
            for (int j2 = 0; j2 < 4; j2++) {
                unsigned r0, r1, r2, r3;
                ldmx4(r0, r1, r2, r3,
                      sK + (unsigned)((16*j2 + (lane & 7) + ((lane >> 4) << 3))*FAE
                                       + kk + (((lane >> 3) & 1) << 3))*2u);
                mma16(s[2*j2],     a0, a1, a2, a3, r0, r1);
                mma16(s[2*j2 + 1], a0, a1, a2, a3, r2, r3);
            }
        }

        float tm0 = -1e30f, tm1 = -1e30f;
        #pragma unroll
        for (int j = 0; j < 8; j++) {
            tm0 = fmaxf(tm0, fmaxf(s[j][0], s[j][1]));
            tm1 = fmaxf(tm1, fmaxf(s[j][2], s[j][3]));
        }
        tm0 = fmaxf(tm0, __shfl_xor_sync(0xffffffffu, tm0, 1));
        tm0 = fmaxf(tm0, __shfl_xor_sync(0xffffffffu, tm0, 2));
        tm1 = fmaxf(tm1, __shfl_xor_sync(0xffffffffu, tm1, 1));
        tm1 = fmaxf(tm1, __shfl_xor_sync(0xffffffffu, tm1, 2));
        float mn0 = fmaxf(m0, tm0), mn1 = fmaxf(m1, tm1);
        float c0 = exp2f(m0 - mn0), c1 = exp2f(m1 - mn1);
        float ps0 = 0.f, ps1 = 0.f;
        #pragma unroll
        for (int j = 0; j < 8; j++) {
            s[j][0] = exp2f(s[j][0] - mn0);
            s[j][1] = exp2f(s[j][1] - mn0);
            s[j][2] = exp2f(s[j][2] - mn1);
            s[j][3] = exp2f(s[j][3] - mn1);
            ps0 += s[j][0] + s[j][1];
            ps1 += s[j][2] + s[j][3];
        }
        ps0 += __shfl_xor_sync(0xffffffffu, ps0, 1);
        ps0 += __shfl_xor_sync(0xffffffffu, ps0, 2);
        ps1 += __shfl_xor_sync(0xffffffffu, ps1, 1);
        ps1 += __shfl_xor_sync(0xffffffffu, ps1, 2);
        l0 = l0 * c0 + ps0;  l1 = l1 * c1 + ps1;
        m0 = mn0;            m1 = mn1;
        #pragma unroll
        for (int j = 0; j < 8; j++) {
            o[j][0] *= c0; o[j][1] *= c0; o[j][2] *= c1; o[j][3] *= c1;
        }

        #pragma unroll
        for (int c = 0; c < 4; c++) {
            unsigned pa0 = pack_bf(s[2*c][0],   s[2*c][1]);
            unsigned pa1 = pack_bf(s[2*c][2],   s[2*c][3]);
            unsigned pa2 = pack_bf(s[2*c+1][0], s[2*c+1][1]);
            unsigned pa3 = pack_bf(s[2*c+1][2], s[2*c+1][3]);
            #pragma unroll
            for (int j2 = 0; j2 < 4; j2++) {
                unsigned r0, r1, r2, r3;
                ldmx4t(r0, r1, r2, r3,
                       sV + (unsigned)((16*c + lm)*FAE + 16*j2 + lh*8)*2u);
                mma16(o[2*j2],     pa0, pa1, pa2, pa3, r0, r1);
                mma16(o[2*j2 + 1], pa0, pa1, pa2, pa3, r2, r3);
            }
        }
    }

    float inv0 = 1.f / l0, inv1 = 1.f / l1;
    #pragma unroll
    for (int j = 0; j < 8; j++) {
        int col = 8*j + 2*t4;
        *(unsigned*)(Ob + (size_t)(q0 + wm + g    )*DIMN + col) = pack_bf(o[j][0]*inv0, o[j][1]*inv0);
        *(unsigned*)(Ob + (size_t)(q0 + wm + g + 8)*DIMN + col) = pack_bf(o[j][2]*inv1, o[j][3]*inv1);
    }
}

// ------- fused residual + norms; branch input bf16; optional patchified output -------
__global__ __launch_bounds__(256) void residual_norm(const float* __restrict__ xb,
                                                     const bf16* __restrict__ br,
                                                     const float* __restrict__ alpha,
                                                     float* __restrict__ out,
                                                     bf16* __restrict__ xp) {
    int t = blockIdx.x;
    int tid = threadIdx.x;
    const float* xr = xb + (size_t)t * DIMN;
    const bf16*  rr = br + (size_t)t * DIMN;
    float xv[4], bv[4];
    float ssx = 0.f, ssb = 0.f;
    #pragma unroll
    for (int u = 0; u < 2; u++) {
        int d = tid*2 + u * 512;
        float2 xx = *(const float2*)(xr + d);
        float2 bb = unpack_bf(*(const unsigned*)(rr + d));
        xv[2*u] = xx.x; xv[2*u+1] = xx.y;
        bv[2*u] = bb.x; bv[2*u+1] = bb.y;
        ssx += xx.x*xx.x + xx.y*xx.y;
        ssb += bb.x*bb.x + bb.y*bb.y;
    }
    ssx = blockSum256(ssx);
    ssb = blockSum256(ssb);
    float rx = 1.f / fmaxf(sqrtf(ssx), 1e-12f);
    float rb = 1.f / fmaxf(sqrtf(ssb), 1e-12f);
    float yv[4]; float ssy = 0.f;
    #pragma unroll
    for (int u = 0; u < 4; u++) {
        int d = tid*2 + (u >> 1) * 512 + (u & 1);
        float hh = xv[u] * rx;
        float ha = bv[u] * rb;
        float lr = fabsf(alpha[d] * 1.6f);
        float y = hh + lr * (ha - hh);
        yv[u] = y; ssy += y * y;
    }
    ssy = blockSum256(ssy);
    float ry = 1.f / fmaxf(sqrtf(ssy), 1e-12f);
    int b = t >> 11, se = t & 2047;
    int ip = se >> 4, p = se & 15;
    #pragma unroll
    for (int u = 0; u < 4; u++) {
        int d = tid*2 + (u >> 1) * 512 + (u & 1);
        float y = yv[u] * ry;
        out[(size_t)t * DIMN + d] = y;
        if (xp) {
            int jj = d >> 4, qq = d & 15;
            xp[((size_t)b*8192 + ip*64 + jj)*256 + p*16 + qq] = __float2bfloat16_rn(y);
        }
    }
}

// ---------------- launch ----------------
extern "C" void kernel_launch(void* const* d_in, const int* in_sizes, int n_in,
                              void* d_out, int out_size) {
    const float* x      = (const float*)d_in[0];
    const float* fcos   = (const float*)d_in[1];
    const float* fsin   = (const float*)d_in[2];
    const float* adafm  = (const float*)d_in[3];
    const float* wq     = (const float*)d_in[4];
    const float* wk     = (const float*)d_in[5];
    const float* wv     = (const float*)d_in[6];
    const float* wo     = (const float*)d_in[7];
    const float* sqk    = (const float*)d_in[8];
    const float* w1     = (const float*)d_in[9];
    const float* w2     = (const float*)d_in[10];
    const float* w3     = (const float*)d_in[11];
    const float* su     = (const float*)d_in[12];
    const float* sv     = (const float*)d_in[13];
    const float* pw     = (const float*)d_in[14];
    const float* pb     = (const float*)d_in[15];
    const float* aalpha = (const float*)d_in[16];
    const float* malpha = (const float*)d_in[17];
    float* out = (float*)d_out;

    float *pt, *ptp, *pf0;
    bf16 *pbgm, *pbgf, *pbxa, *pbq, *pbk, *pbv, *pbao, *pbwo, *pbxp;
    unsigned char *pxm8;
    cudaGetSymbolAddress((void**)&pt,  d_t);
    cudaGetSymbolAddress((void**)&ptp, d_tp);
    cudaGetSymbolAddress((void**)&pf0, d_f0);
    cudaGetSymbolAddress((void**)&pbgm, b_gm);
    cudaGetSymbolAddress((void**)&pbgf, b_gf);
    cudaGetSymbolAddress((void**)&pbxa, b_xa);
    cudaGetSymbolAddress((void**)&pbq,  b_q);
    cudaGetSymbolAddress((void**)&pbk,  b_k);
    cudaGetSymbolAddress((void**)&pbv,  b_v);
    cudaGetSymbolAddress((void**)&pbao, b_ao);
    cudaGetSymbolAddress((void**)&pbwo, b_wo);
    cudaGetSymbolAddress((void**)&pbxp, b_xp);
    cudaGetSymbolAddress((void**)&pxm8, b_xm8);

    cudaFuncSetAttribute(gemm_bf16o, cudaFuncAttributeMaxDynamicSharedMemorySize, GEMM_SMEM);
    cudaFuncSetAttribute(gemm_qkv, cudaFuncAttributeMaxDynamicSharedMemorySize, GEMM_SMEM);
    cudaFuncSetAttribute(adafm_gemm, cudaFuncAttributeMaxDynamicSharedMemorySize, GEMM_SMEM);
    cudaFuncSetAttribute(gemm_ffn13f8, cudaFuncAttributeMaxDynamicSharedMemorySize, FFN8_SMEM);
    cudaFuncSetAttribute(gemm_w2f8, cudaFuncAttributeMaxDynamicSharedMemorySize, W2F8_SMEM);
    cudaFuncSetAttribute(flash_attn, cudaFuncAttributeMaxDynamicSharedMemorySize, FLASH_SMEM);

    // 0) weight conversions
    cvt_all<<<dim3(256, 4), 256>>>(wq, wk, wv, wo);
    cvt_w13t<<<dim3(2816, 2), 256>>>(w1, w3);
    cvt_w2t<<<2816, 256>>>(w2);

    // 1) time-modulation (split-K proj_t)
    proj_t_part<<<dim3(BATCH, 16, 8), 256>>>(adafm, pw, ptp);
    proj_t_red<<<4, 256>>>(ptp, pb, pt);
    make_g_kernel<<<dim3(4, 32), 256>>>(pt);

    // 2) attention branch
    patchify<<<2048, 256>>>(x);
    adafm_gemm<<<dim3(1, 64, 2), 256, GEMM_SMEM>>>(pbgm, pbxa, (unsigned char*)0);
    gemm_qkv<<<dim3(12, 32), 256, GEMM_SMEM>>>(pbxa, fcos, fsin, sqk);
    flash_attn<<<dim3(SEQL/128, NHEAD, BATCH), 256, FLASH_SMEM>>>(pbq, pbk, pbv, pbao);
    gemm_bf16o<<<dim3(DIMN/256, TOK/128), 256, GEMM_SMEM>>>(pbao, pbwo, pbq, TOK, DIMN, DIMN);
    residual_norm<<<TOK, 256>>>(x, pbq, aalpha, pf0, pbxp);

    // 3) FFN branch (fp8)
    adafm_gemm<<<dim3(1, 64, 2), 256, GEMM_SMEM>>>(pbgf, (bf16*)0, pxm8);
    gemm_ffn13f8<<<dim3(HIDDEN/128, TOK/128), 256, FFN8_SMEM>>>(su, sv);
    gemm_w2f8<<<dim3(DIMN/256, TOK/128), 256, W2F8_SMEM>>>(pbk);
    residual_norm<<<TOK, 256>>>(pf0, pbk, malpha, out, (bf16*)0);
}

// round 17
// speedup vs baseline: 7.7440x; 1.0070x over previous
#include <cuda_runtime.h>
#include <cuda_bf16.h>
#include <cuda_fp8.h>
#include <math.h>

typedef __nv_bfloat16 bf16;

#define DIMN   1024
#define NHEAD  16
#define HDIM   64
#define SEQL   2048
#define BATCH  2
#define TOK    4096
#define HIDDEN 2816

__device__ float d_tp[BATCH*512*8];
__device__ float d_f0[TOK*DIMN];

__device__ bf16 b_wq[DIMN*DIMN], b_wk[DIMN*DIMN], b_wv[DIMN*DIMN], b_wo[DIMN*DIMN];
__device__ unsigned char b_w13t[(size_t)2*HIDDEN*DIMN];
__device__ unsigned char b_w2t[(size_t)DIMN*HIDDEN];
__device__ bf16 b_xp[BATCH*8192*256];
__device__ bf16 b_gm[BATCH*256*256];
__device__ bf16 b_gf[BATCH*256*256];
__device__ bf16 b_xa[TOK*DIMN];
__device__ unsigned char b_xm8[TOK*DIMN];
__device__ bf16 b_q [TOK*DIMN], b_k[TOK*DIMN], b_v[TOK*DIMN], b_ao[TOK*DIMN];
__device__ unsigned char b_h8[(size_t)TOK*HIDDEN];

__device__ __forceinline__ float blockSum256(float v) {
    __shared__ float red[8];
    int lane = threadIdx.x & 31, wid = threadIdx.x >> 5;
    #pragma unroll
    for (int o = 16; o > 0; o >>= 1) v += __shfl_xor_sync(0xffffffffu, v, o);
    __syncthreads();
    if (lane == 0) red[wid] = v;
    __syncthreads();
    float s = red[0];
    #pragma unroll
    for (int w = 1; w < 8; w++) s += red[w];
    return s;
}
__device__ __forceinline__ void mma16(float* c, unsigned a0, unsigned a1, unsigned a2, unsigned a3,
                                      unsigned b0, unsigned b1) {
    asm volatile("mma.sync.aligned.m16n8k16.row.col.f32.bf16.bf16.f32 "
        "{%0,%1,%2,%3}, {%4,%5,%6,%7}, {%8,%9}, {%0,%1,%2,%3};"
        : "+f"(c[0]), "+f"(c[1]), "+f"(c[2]), "+f"(c[3])
        : "r"(a0), "r"(a1), "r"(a2), "r"(a3), "r"(b0), "r"(b1));
}
__device__ __forceinline__ void mma8f8(float* c, unsigned a0, unsigned a1, unsigned a2, unsigned a3,
                                       unsigned b0, unsigned b1) {
    asm volatile("mma.sync.aligned.m16n8k32.row.col.f32.e4m3.e4m3.f32 "
        "{%0,%1,%2,%3}, {%4,%5,%6,%7}, {%8,%9}, {%0,%1,%2,%3};"
        : "+f"(c[0]), "+f"(c[1]), "+f"(c[2]), "+f"(c[3])
        : "r"(a0), "r"(a1), "r"(a2), "r"(a3), "r"(b0), "r"(b1));
}
__device__ __forceinline__ void ldmx4(unsigned& r0, unsigned& r1, unsigned& r2, unsigned& r3, unsigned a) {
    asm volatile("ldmatrix.sync.aligned.m8n8.x4.shared.b16 {%0,%1,%2,%3}, [%4];"
                 : "=r"(r0), "=r"(r1), "=r"(r2), "=r"(r3) : "r"(a));
}
__device__ __forceinline__ void ldmx4t(unsigned& r0, unsigned& r1, unsigned& r2, unsigned& r3, unsigned a) {
    asm volatile("ldmatrix.sync.aligned.m8n8.x4.trans.shared.b16 {%0,%1,%2,%3}, [%4];"
                 : "=r"(r0), "=r"(r1), "=r"(r2), "=r"(r3) : "r"(a));
}
__device__ __forceinline__ void cpa16(unsigned s, const void* g) {
    asm volatile("cp.async.cg.shared.global [%0], [%1], 16;" :: "r"(s), "l"(g));
}
__device__ __forceinline__ unsigned pack_bf(float a, float b) {
    __nv_bfloat162 t; t.x = __float2bfloat16_rn(a); t.y = __float2bfloat16_rn(b);
    return *(unsigned*)&t;
}
__device__ __forceinline__ float2 unpack_bf(unsigned u) {
    __nv_bfloat162 t = *(__nv_bfloat162*)&u;
    return make_float2(__bfloat162float(t.x), __bfloat162float(t.y));
}
__device__ __forceinline__ unsigned short pack_f8(float lo, float hi) {
    unsigned short r;
    asm("cvt.rn.satfinite.e4m3x2.f32 %0, %1, %2;" : "=h"(r) : "f"(hi), "f"(lo));
    return r;
}

// ---- all weight conversions, single launch: blocks [0,1024) bf16, [1024,6656) w13t, rest w2t ----
__global__ void cvt_mega(const float* __restrict__ s0, const float* __restrict__ s1,
                         const float* __restrict__ s2, const float* __restrict__ s3,
                         const float* __restrict__ sw1, const float* __restrict__ sw3,
                         const float* __restrict__ sw2) {
    __shared__ float sT[32][33];
    int blk = blockIdx.x;
    if (blk < 1024) {
        int w = blk >> 8;
        const float* src = (w == 0) ? s0 : (w == 1 ? s1 : (w == 2 ? s2 : s3));
        bf16* dst = (w == 0) ? b_wq : (w == 1 ? b_wk : (w == 2 ? b_wv : b_wo));
        int i = ((blk & 255) * 256 + threadIdx.x) * 16;
        float4 a = *(const float4*)(src + i);
        float4 b = *(const float4*)(src + i + 4);
        float4 c = *(const float4*)(src + i + 8);
        float4 d = *(const float4*)(src + i + 12);
        uint4 o1, o2;
        o1.x = pack_bf(a.x, a.y); o1.y = pack_bf(a.z, a.w);
        o1.z = pack_bf(b.x, b.y); o1.w = pack_bf(b.z, b.w);
        o2.x = pack_bf(c.x, c.y); o2.y = pack_bf(c.z, c.w);
        o2.z = pack_bf(d.x, d.y); o2.w = pack_bf(d.z, d.w);
        *(uint4*)(dst + i) = o1;
        *(uint4*)(dst + i + 8) = o2;
    } else if (blk < 6656) {
        int idx2 = blk - 1024;
        int wsel = idx2 / 2816, bx = idx2 % 2816;
        const float* src = wsel ? sw3 : sw1;
        unsigned char* dst = b_w13t + (wsel ? (size_t)HIDDEN*DIMN : 0);
        int kt = bx / 88, nt = bx % 88;
        int tx = threadIdx.x & 31, ty0 = threadIdx.x >> 5;
        #pragma unroll
        for (int it = 0; it < 4; it++)
            sT[ty0 + 8*it][tx] = src[(size_t)(kt*32 + ty0 + 8*it) * HIDDEN + nt*32 + tx];
        __syncthreads();
        #pragma unroll
        for (int it = 0; it < 4; it++) {
            int row = ty0 + 8*it;
            __nv_fp8_e4m3 v(sT[tx][row] * 256.f);
            dst[(size_t)(nt*32 + row) * DIMN + kt*32 + tx] = *(unsigned char*)&v;
        }
    } else {
        int bx = blk - 6656;
        int kt = bx >> 5, nt = bx & 31;
        int tx = threadIdx.x & 31, ty0 = threadIdx.x >> 5;
        #pragma unroll
        for (int it = 0; it < 4; it++)
            sT[ty0 + 8*it][tx] = sw2[(size_t)(kt*32 + ty0 + 8*it) * DIMN + nt*32 + tx];
        __syncthreads();
        #pragma unroll
        for (int it = 0; it < 4; it++) {
            int row = ty0 + 8*it;
            __nv_fp8_e4m3 v(sT[tx][row] * 64.f);
            b_w2t[(size_t)(nt*32 + row) * HIDDEN + kt*32 + tx] = *(unsigned char*)&v;
        }
    }
}

// -------- proj_t split-K partials: grid (BATCH, 16, 8) --------
__global__ void proj_t_part(const float* __restrict__ ad, const float* __restrict__ pw,
                            float* __restrict__ tp) {
    int b = blockIdx.x, o0 = blockIdx.y * 32, z = blockIdx.z;
    __shared__ float s[128];
    __shared__ float red[8][32];
    int tid = threadIdx.x;
    if (tid < 128) {
        float zz = ad[b*DIMN + z*128 + tid];
        s[tid] = zz / (1.f + expf(-zz));
    }
    __syncthreads();
    int warp = tid >> 5, lane = tid & 31;
    const float* pwc = pw + (size_t)(z*128)*512 + o0 + lane;
    float acc = 0.f;
    #pragma unroll
    for (int i = warp*16; i < warp*16 + 16; i++)
        acc += s[i] * pwc[(size_t)i*512];
    red[warp][lane] = acc;
    __syncthreads();
    if (tid < 32)
        tp[((size_t)(b*512 + o0 + tid))*8 + z]
            = red[0][tid] + red[1][tid] + red[2][tid] + red[3][tid]
            + red[4][tid] + red[5][tid] + red[6][tid] + red[7][tid];
}

// ---- make_g: reduces partials inline; grid (4, 32) ----
__global__ void make_g_kernel(const float* __restrict__ tp, const float* __restrict__ pb) {
    int b = blockIdx.x >> 1, which = blockIdx.x & 1;
    int q0 = blockIdx.y * 8;
    __shared__ float cs[256], ms[256];
    __shared__ bf16 gd[512];
    int d = threadIdx.x;
    cs[d] = cosf((6.283185307179586f / 256.0f) * (float)d);
    {
        int idx = b*512 + which*256 + d;
        const float* p = tp + (size_t)idx * 8;
        float r = pb[which*256 + d];
        #pragma unroll
        for (int z = 0; z < 8; z++) r += p[z];
        ms[d] = r;
    }
    __syncthreads();
    float acc = 0.f;
    #pragma unroll 4
    for (int k = 0; k < 256; k++) acc += ms[k] * cs[(k*d) & 255];
    bf16 gv = __float2bfloat16_rn(acc * (1.0f / 256.0f));
    gd[d] = gv; gd[d + 256] = gv;
    __syncthreads();
    bf16* Bg = (which ? b_gf : b_gm) + b * 65536;
    #pragma unroll
    for (int q = q0; q < q0 + 8; q++)
        Bg[q*256 + d] = gd[d - q + 256];
}

__global__ void patchify(const float* __restrict__ x) {
    int c = blockIdx.x * 256 + threadIdx.x;
    int q  = (c & 31) * 8;
    int pi = (c >> 5) & 8191;
    int b  = c >> 18;
    int p = q >> 4, qq = q & 15;
    const float* src = x + ((size_t)(b*2048 + (pi >> 6)*16 + p)) * DIMN + (pi & 63)*16 + qq;
    float4 a = *(const float4*)src;
    float4 v = *(const float4*)(src + 4);
    uint4 o;
    o.x = pack_bf(a.x, a.y); o.y = pack_bf(a.z, a.w);
    o.z = pack_bf(v.x, v.y); o.w = pack_bf(v.z, v.w);
    *(uint4*)(b_xp + (size_t)c * 8) = o;
}

// ================= bf16 GEMM core (6-stage ring, 2 k-tiles per barrier) =================
#define AKE 40
#define BNE 264
#define A_ELT (128*AKE)
#define B_ELT (32*BNE)
#define STG_ELT (A_ELT + B_ELT)
#define GEMM_SMEM (6 * STG_ELT * 2)

#define GEMM_PROLOG(Aptr, Bptr, Kdim, Ndim, bmv, bnv)                                    \
    extern __shared__ bf16 smb[];                                                        \
    const unsigned sbase = (unsigned)__cvta_generic_to_shared(smb);                      \
    const int tid  = threadIdx.x;                                                        \
    const int lane = tid & 31;                                                           \
    const int warp = tid >> 5;                                                           \
    const int g    = lane >> 2;                                                          \
    const int t4   = lane & 3;                                                           \
    const int lm   = lane & 15;                                                          \
    const int lh   = lane >> 4;                                                          \
    const int wm = (warp >> 2) * 64;                                                     \
    const int wn = (warp & 3) * 64;                                                      \
    float acc[4][8][4];                                                                  \
    _Pragma("unroll") for (int i = 0; i < 4; i++)                                        \
        _Pragma("unroll") for (int j = 0; j < 8; j++)                                    \
            _Pragma("unroll") for (int r = 0; r < 4; r++) acc[i][j][r] = 0.f;            \
    const int ktiles = (Kdim) >> 5;                                                      \
    auto load_stage = [&](int st, int k0) {                                              \
        unsigned sa = sbase + (unsigned)(st * STG_ELT) * 2u;                             \
        unsigned sb = sa + A_ELT * 2u;                                                   \
        _Pragma("unroll") for (int u = 0; u < 2; u++) {                                  \
            int c = tid + 256*u;                                                         \
            int r = c >> 2, o = (c & 3) * 8;                                             \
            cpa16(sa + (unsigned)(r*AKE + o)*2u, (Aptr) + (size_t)((bmv) + r) * (Kdim) + k0 + o); \
        }                                                                                \
        _Pragma("unroll") for (int u = 0; u < 4; u++) {                                  \
            int c = tid + 256*u;                                                         \
            int r = c >> 5, o = (c & 31) * 8;                                            \
            cpa16(sb + (unsigned)(r*BNE + o)*2u, (Bptr) + (size_t)(k0 + r) * (Ndim) + (bnv) + o); \
        }                                                                                \
    };                                                                                   \
    load_stage(0, 0);                                                                    \
    asm volatile("cp.async.commit_group;");                                              \
    load_stage(1, 32);                                                                   \
    asm volatile("cp.async.commit_group;");                                              \
    load_stage(2, 64);                                                                   \
    asm volatile("cp.async.commit_group;");                                              \
    load_stage(3, 96);                                                                   \
    asm volatile("cp.async.commit_group;");                                              \
    for (int t = 0; t < ktiles; t += 2) {                                                \
        asm volatile("cp.async.wait_group 2;");                                          \
        __syncthreads();                                                                 \
        if (t + 4 < ktiles) load_stage((t + 4) % 6, (t + 4) * 32);                       \
        asm volatile("cp.async.commit_group;");                                          \
        if (t + 5 < ktiles) load_stage((t + 5) % 6, (t + 5) * 32);                       \
        asm volatile("cp.async.commit_group;");                                          \
        _Pragma("unroll") for (int hh = 0; hh < 2; hh++) {                               \
            unsigned sa = sbase + (unsigned)(((t + hh) % 6) * STG_ELT) * 2u;             \
            unsigned sb = sa + A_ELT * 2u;                                               \
            _Pragma("unroll") for (int kk = 0; kk < 32; kk += 16) {                      \
                unsigned af[4][4], bfr[8][2];                                            \
                _Pragma("unroll") for (int i = 0; i < 4; i++)                            \
                    ldmx4(af[i][0], af[i][1], af[i][2], af[i][3],                        \
                          sa + (unsigned)((wm + 16*i + lm)*AKE + kk + lh*8)*2u);         \
                _Pragma("unroll") for (int j2 = 0; j2 < 4; j2++)                         \
                    ldmx4t(bfr[2*j2][0], bfr[2*j2][1], bfr[2*j2+1][0], bfr[2*j2+1][1],   \
                           sb + (unsigned)((kk + lm)*BNE + wn + 16*j2 + lh*8)*2u);       \
                _Pragma("unroll") for (int i = 0; i < 4; i++)                            \
                    _Pragma("unroll") for (int j = 0; j < 8; j++)                        \
                        mma16(acc[i][j], af[i][0], af[i][1], af[i][2], af[i][3],         \
                              bfr[j][0], bfr[j][1]);                                     \
            }                                                                            \
        }                                                                                \
    }

__global__ __launch_bounds__(256, 1) void gemm_bf16o(const bf16* __restrict__ A,
                                                     const bf16* __restrict__ B,
                                                     bf16* __restrict__ Cb,
                                                     int M, int N, int K) {
    const int bm = blockIdx.y * 128;
    const int bn = blockIdx.x * 256;
    GEMM_PROLOG(A, B, K, N, bm, bn)
    #pragma unroll
    for (int i = 0; i < 4; i++) {
        int row0 = bm + wm + 16*i + g;
        #pragma unroll
        for (int j = 0; j < 8; j++) {
            int col = bn + wn + 8*j + 2*t4;
            *(unsigned*)(Cb + (size_t)row0 * N + col)       = pack_bf(acc[i][j][0], acc[i][j][1]);
            *(unsigned*)(Cb + (size_t)(row0 + 8) * N + col) = pack_bf(acc[i][j][2], acc[i][j][3]);
        }
    }
}

__global__ __launch_bounds__(256, 1) void gemm_qkv(const bf16* __restrict__ A,
                                                   const float* __restrict__ fcos,
                                                   const float* __restrict__ fsin,
                                                   const float* __restrict__ sqk) {
    const int wsel = blockIdx.x >> 2;
    const int bn = (blockIdx.x & 3) * 256;
    const int bm = blockIdx.y * 128;
    const bf16* B = (wsel == 0) ? b_wq : ((wsel == 1) ? b_wk : b_wv);
    bf16* C = (wsel == 0) ? b_q : ((wsel == 1) ? b_k : b_v);
    GEMM_PROLOG(A, B, DIMN, DIMN, bm, bn)
    if (wsel == 2) {
        #pragma unroll
        for (int i = 0; i < 4; i++) {
            int row0 = bm + wm + 16*i + g;
            #pragma unroll
            for (int j = 0; j < 8; j++) {
                int col = bn + wn + 8*j + 2*t4;
                *(unsigned*)(C + (size_t)row0 * DIMN + col)       = pack_bf(acc[i][j][0], acc[i][j][1]);
                *(unsigned*)(C + (size_t)(row0 + 8) * DIMN + col) = pack_bf(acc[i][j][2], acc[i][j][3]);
            }
        }
    } else {
        const int h = (bn + wn) >> 6;
        const float qscale = (wsel == 0) ? 8.f * 1.4426950408889634f : 1.f;
        #pragma unroll
        for (int i = 0; i < 4; i++) {
            int row0 = bm + wm + 16*i + g;
            int row1 = row0 + 8;
            float ss0 = 0.f, ss1 = 0.f;
            #pragma unroll
            for (int j = 0; j < 8; j++) {
                ss0 += acc[i][j][0]*acc[i][j][0] + acc[i][j][1]*acc[i][j][1];
                ss1 += acc[i][j][2]*acc[i][j][2] + acc[i][j][3]*acc[i][j][3];
            }
            ss0 += __shfl_xor_sync(0xffffffffu, ss0, 1);
            ss0 += __shfl_xor_sync(0xffffffffu, ss0, 2);
            ss1 += __shfl_xor_sync(0xffffffffu, ss1, 1);
            ss1 += __shfl_xor_sync(0xffffffffu, ss1, 2);
            float inv0 = qscale / fmaxf(sqrtf(ss0), 1e-12f);
            float inv1 = qscale / fmaxf(sqrtf(ss1), 1e-12f);
            int s0 = row0 & (SEQL - 1), s1 = row1 & (SEQL - 1);
            #pragma unroll
            for (int j = 0; j < 8; j++) {
                int pidx = 4*j + t4;
                int d = 8*j + 2*t4;
                float se0 = sqk[h*HDIM + d]     * 32.f;
                float se1 = sqk[h*HDIM + d + 1] * 32.f;
                float c0 = fcos[s0*32 + pidx], sn0 = fsin[s0*32 + pidx];
                float c1 = fcos[s1*32 + pidx], sn1 = fsin[s1*32 + pidx];
                float a0 = acc[i][j][0], a1 = acc[i][j][1];
                float b0 = acc[i][j][2], b1 = acc[i][j][3];
                int col = bn + wn + d;
                *(unsigned*)(C + (size_t)row0 * DIMN + col) =
                    pack_bf((a0*c0 - a1*sn0) * inv0 * se0, (a0*sn0 + a1*c0) * inv0 * se1);
                *(unsigned*)(C + (size_t)row1 * DIMN + col) =
                    pack_bf((b0*c1 - b1*sn1) * inv1 * se0, (b0*sn1 + b1*c1) * inv1 * se1);
            }
        }
    }
}

__global__ __launch_bounds__(256, 1) void adafm_gemm(const bf16* __restrict__ Bg0,
                                                     bf16* __restrict__ Y,
                                                     unsigned char* __restrict__ Y8) {
    const int z  = blockIdx.z;
    const int bm = blockIdx.y * 128;
    const int bn = 0;
    const bf16* A = b_xp + (size_t)z * 8192 * 256;
    const bf16* B = Bg0 + (size_t)z * 65536;
    GEMM_PROLOG(A, B, 256, 256, bm, bn)
    #pragma unroll
    for (int i = 0; i < 4; i++) {
        int pi0 = bm + wm + 16*i + g;
        #pragma unroll
        for (int j = 0; j < 8; j++) {
            int col = wn + 8*j + 2*t4;
            int p = col >> 4, qq = col & 15;
            int pi1 = pi0 + 8;
            size_t off0 = (size_t)(z*2048 + (pi0 >> 6)*16 + p) * DIMN + (pi0 & 63)*16 + qq;
            size_t off1 = (size_t)(z*2048 + (pi1 >> 6)*16 + p) * DIMN + (pi1 & 63)*16 + qq;
            if (Y8) {
                *(unsigned short*)(Y8 + off0) = pack_f8(acc[i][j][0]*16.f, acc[i][j][1]*16.f);
                *(unsigned short*)(Y8 + off1) = pack_f8(acc[i][j][2]*16.f, acc[i][j][3]*16.f);
            } else {
                *(unsigned*)(Y + off0) = pack_bf(acc[i][j][0], acc[i][j][1]);
                *(unsigned*)(Y + off1) = pack_bf(acc[i][j][2], acc[i][j][3]);
            }
        }
    }
}

// ================= fp8 GEMMs (6-stage ring, 2 k64-tiles per barrier) =================
#define F8AS 80
#define F8STG (128*F8AS + 256*F8AS)
#define FFN8_SMEM (6 * F8STG)

__global__ __launch_bounds__(256, 1) void gemm_ffn13f8(const float* __restrict__ su,
                                                       const float* __restrict__ sv) {
    const int bnb = blockIdx.x * 128;
    const int bm  = blockIdx.y * 128;
    extern __shared__ __align__(16) unsigned char sm8[];
    const unsigned sbase = (unsigned)__cvta_generic_to_shared(sm8);
    const int tid  = threadIdx.x;
    const int lane = tid & 31;
    const int warp = tid >> 5;
    const int g    = lane >> 2;
    const int t4   = lane & 3;
    const int lm   = lane & 15;
    const int lh   = lane >> 4;
    const int wm = (warp >> 2) * 64;
    const int wn = (warp & 3) * 32;
    const int q8 = lane >> 3, r8 = lane & 7;

    float acc1[4][4][4], acc3[4][4][4];
    #pragma unroll
    for (int i = 0; i < 4; i++)
        #pragma unroll
        for (int j = 0; j < 4; j++)
            #pragma unroll
            for (int r = 0; r < 4; r++) { acc1[i][j][r] = 0.f; acc3[i][j][r] = 0.f; }

    const int ktiles = DIMN >> 6;
    auto load_stage = [&](int st, int k0) {
        unsigned sa = sbase + (unsigned)(st * F8STG);
        unsigned sb = sa + 128*F8AS;
        #pragma unroll
        for (int u = 0; u < 2; u++) {
            int c = tid + 256*u;
            int r = c >> 2, o = (c & 3) * 16;
            cpa16(sa + (unsigned)(r*F8AS + o), b_xm8 + (size_t)(bm + r) * DIMN + k0 + o);
        }
        #pragma unroll
        for (int u = 0; u < 4; u++) {
            int c = tid + 256*u;
            int r = c >> 2, o = (c & 3) * 16;
            const unsigned char* src = (r < 128)
                ? (b_w13t + (size_t)(bnb + r) * DIMN)
                : (b_w13t + (size_t)HIDDEN*DIMN + (size_t)(bnb + r - 128) * DIMN);
            cpa16(sb + (unsigned)(r*F8AS + o), src + k0 + o);
        }
    };
    load_stage(0, 0);
    asm volatile("cp.async.commit_group;");
    load_stage(1, 64);
    asm volatile("cp.async.commit_group;");
    load_stage(2, 128);
    asm volatile("cp.async.commit_group;");
    load_stage(3, 192);
    asm volatile("cp.async.commit_group;");

    for (int t = 0; t < ktiles; t += 2) {
        asm volatile("cp.async.wait_group 2;");
        __syncthreads();
        if (t + 4 < ktiles) load_stage((t + 4) % 6, (t + 4) * 64);
        asm volatile("cp.async.commit_group;");
        if (t + 5 < ktiles) load_stage((t + 5) % 6, (t + 5) * 64);
        asm volatile("cp.async.commit_group;");
        #pragma unroll
        for (int hh = 0; hh < 2; hh++) {
            unsigned sa = sbase + (unsigned)(((t + hh) % 6) * F8STG);
            unsigned sb = sa + 128*F8AS;
            #pragma unroll
            for (int ks = 0; ks < 2; ks++) {
                int k0 = ks * 32;
                unsigned af[4][4], b1f[4][2], b3f[4][2];
                #pragma unroll
                for (int i = 0; i < 4; i++)
                    ldmx4(af[i][0], af[i][1], af[i][2], af[i][3],
                          sa + (unsigned)((wm + 16*i + lm)*F8AS + k0 + lh*16));
                #pragma unroll
                for (int jp = 0; jp < 2; jp++) {
                    int n0 = wn + 16*jp;
                    unsigned ra = (unsigned)((n0 + ((q8 >> 1) << 3) + r8)*F8AS + k0 + ((q8 & 1) << 4));
                    ldmx4(b1f[2*jp][0], b1f[2*jp][1], b1f[2*jp+1][0], b1f[2*jp+1][1], sb + ra);
                    ldmx4(b3f[2*jp][0], b3f[2*jp][1], b3f[2*jp+1][0], b3f[2*jp+1][1],
                          sb + 128u*F8AS + ra);
                }
                #pragma unroll
                for (int i = 0; i < 4; i++)
                    #pragma unroll
                    for (int j = 0; j < 4; j++) {
                        mma8f8(acc1[i][j], af[i][0], af[i][1], af[i][2], af[i][3], b1f[j][0], b1f[j][1]);
                        mma8f8(acc3[i][j], af[i][0], af[i][1], af[i][2], af[i][3], b3f[j][0], b3f[j][1]);
                    }
            }
        }
    }

    const float SC = 53.06599664568481f;
    const float OS13 = 1.f / 4096.f;
    #pragma unroll
    for (int i = 0; i < 4; i++) {
        int row0 = bm + wm + 16*i + g;
        #pragma unroll
        for (int j = 0; j < 4; j++) {
            int col = bnb + wn + 8*j + 2*t4;
            float sv0 = sv[col] * SC * OS13, sv1 = sv[col+1] * SC * OS13;
            float su0 = su[col] * OS13,      su1 = su[col+1] * OS13;
            float z, sgl, outv[4];
            z = acc1[i][j][0] * sv0; sgl = z / (1.f + __expf(-z)); outv[0] = sgl * (acc3[i][j][0] * su0);
            z = acc1[i][j][1] * sv1; sgl = z / (1.f + __expf(-z)); outv[1] = sgl * (acc3[i][j][1] * su1);
            z = acc1[i][j][2] * sv0; sgl = z / (1.f + __expf(-z)); outv[2] = sgl * (acc3[i][j][2] * su0);
            z = acc1[i][j][3] * sv1; sgl = z / (1.f + __expf(-z)); outv[3] = sgl * (acc3[i][j][3] * su1);
            *(unsigned short*)(b_h8 + (size_t)row0 * HIDDEN + col)
                = pack_f8(outv[0]*256.f, outv[1]*256.f);
            *(unsigned short*)(b_h8 + (size_t)(row0 + 8) * HIDDEN + col)
                = pack_f8(outv[2]*256.f, outv[3]*256.f);
        }
    }
}

#define A8S 80
#define STG8 (128*A8S + 256*A8S)
#define W2F8_SMEM (6 * STG8)

__global__ __launch_bounds__(256, 1) void gemm_w2f8(bf16* __restrict__ Cb) {
    const int bm = blockIdx.y * 128;
    const int bn = blockIdx.x * 256;
    extern __shared__ __align__(16) unsigned char sm8[];
    const unsigned sbase = (unsigned)__cvta_generic_to_shared(sm8);
    const int tid  = threadIdx.x;
    const int lane = tid & 31;
    const int warp = tid >> 5;
    const int g    = lane >> 2;
    const int t4   = lane & 3;
    const int lm   = lane & 15;
    const int lh   = lane >> 4;
    const int wm = (warp >> 2) * 64;
    const int wn = (warp & 3) * 64;
    const int q8 = lane >> 3, r8 = lane & 7;

    float acc[4][8][4];
    #pragma unroll
    for (int i = 0; i < 4; i++)
        #pragma unroll
        for (int j = 0; j < 8; j++)
            #pragma unroll
            for (int r = 0; r < 4; r++) acc[i][j][r] = 0.f;

    const int ktiles = HIDDEN >> 6;   // 44
    auto load_stage = [&](int st, int k0) {
        unsigned sa = sbase + (unsigned)(st * STG8);
        unsigned sb = sa + 128*A8S;
        #pragma unroll
        for (int u = 0; u < 2; u++) {
            int c = tid + 256*u;
            int r = c >> 2, o = (c & 3) * 16;
            cpa16(sa + (unsigned)(r*A8S + o), b_h8 + (size_t)(bm + r) * HIDDEN + k0 + o);
        }
        #pragma unroll
        for (int u = 0; u < 4; u++) {
            int c = tid + 256*u;
            int r = c >> 2, o = (c & 3) * 16;
            cpa16(sb + (unsigned)(r*A8S + o), b_w2t + (size_t)(bn + r) * HIDDEN + k0 + o);
        }
    };
    load_stage(0, 0);
    asm volatile("cp.async.commit_group;");
    load_stage(1, 64);
    asm volatile("cp.async.commit_group;");
    load_stage(2, 128);
    asm volatile("cp.async.commit_group;");
    load_stage(3, 192);
    asm volatile("cp.async.commit_group;");

    for (int t = 0; t < ktiles; t += 2) {
        asm volatile("cp.async.wait_group 2;");
        __syncthreads();
        if (t + 4 < ktiles) load_stage((t + 4) % 6, (t + 4) * 64);
        asm volatile("cp.async.commit_group;");
        if (t + 5 < ktiles) load_stage((t + 5) % 6, (t + 5) * 64);
        asm volatile("cp.async.commit_group;");
        #pragma unroll
        for (int hh = 0; hh < 2; hh++) {
            unsigned sa = sbase + (unsigned)(((t + hh) % 6) * STG8);
            unsigned sb = sa + 128*A8S;
            #pragma unroll
            for (int ks = 0; ks < 2; ks++) {
                int k0 = ks * 32;
                unsigned af[4][4], bfr[8][2];
                #pragma unroll
                for (int i = 0; i < 4; i++)
                    ldmx4(af[i][0], af[i][1], af[i][2], af[i][3],
                          sa + (unsigned)((wm + 16*i + lm)*A8S + k0 + lh*16));
                #pragma unroll
                for (int jp = 0; jp < 4; jp++) {
                    int n0 = wn + 16*jp;
                    unsigned addr = sb + (unsigned)((n0 + ((q8 >> 1) << 3) + r8)*A8S + k0 + ((q8 & 1) << 4));
                    ldmx4(bfr[2*jp][0], bfr[2*jp][1], bfr[2*jp+1][0], bfr[2*jp+1][1], addr);
                }
                #pragma unroll
                for (int i = 0; i < 4; i++)
                    #pragma unroll
                    for (int j = 0; j < 8; j++)
                        mma8f8(acc[i][j], af[i][0], af[i][1], af[i][2], af[i][3],
                               bfr[j][0], bfr[j][1]);
            }
        }
    }

    const float OS = 1.f / 16384.f;
    #pragma unroll
    for (int i = 0; i < 4; i++) {
        int row0 = bm + wm + 16*i + g;
        #pragma unroll
        for (int j = 0; j < 8; j++) {
            int col = bn + wn + 8*j + 2*t4;
            *(unsigned*)(Cb + (size_t)row0 * DIMN + col)       = pack_bf(acc[i][j][0]*OS, acc[i][j][1]*OS);
            *(unsigned*)(Cb + (size_t)(row0 + 8) * DIMN + col) = pack_bf(acc[i][j][2]*OS, acc[i][j][3]*OS);
        }
    }
}

// --------- FA2 flash attention, cp.async 3-stage ring ---------
#define FAE 72
#define FLASH_SMEM ((128 + 6*64) * FAE * 2)

__global__ __launch_bounds__(256, 2) void flash_attn(const bf16* __restrict__ Q,
                                                     const bf16* __restrict__ K,
                                                     const bf16* __restrict__ V,
                                                     bf16* __restrict__ O) {
    extern __shared__ bf16 fsm[];
    bf16* Qs = fsm;
    const unsigned sQ  = (unsigned)__cvta_generic_to_shared(Qs);
    const unsigned sK0 = sQ + 128*FAE*2u;
    const unsigned sV0 = sK0 + 3*64*FAE*2u;

    const int q0 = blockIdx.x * 128;
    const int h  = blockIdx.y;
    const int b  = blockIdx.z;
    const bf16* Qb = Q + (size_t)b*SEQL*DIMN + h*HDIM;
    const bf16* Kb = K + (size_t)b*SEQL*DIMN + h*HDIM;
    const bf16* Vb = V + (size_t)b*SEQL*DIMN + h*HDIM;
    bf16*       Ob = O + (size_t)b*SEQL*DIMN + h*HDIM;

    const int tid  = threadIdx.x;
    const int lane = tid & 31;
    const int warp = tid >> 5;
    const int g  = lane >> 2;
    const int t4 = lane & 3;
    const int lm = lane & 15;
    const int lh = lane >> 4;
    const int wm = warp * 16;

    auto loadKV = [&](int st, int k0) {
        unsigned sk = sK0 + (unsigned)st * 64*FAE*2u;
        unsigned sv = sV0 + (unsigned)st * 64*FAE*2u;
        #pragma unroll
        for (int u = 0; u < 2; u++) {
            int c = tid + 256*u;
            int r = c >> 3, ofs = (c & 7) * 8;
            cpa16(sk + (unsigned)(r*FAE + ofs)*2u, Kb + (size_t)(k0 + r)*DIMN + ofs);
            cpa16(sv + (unsigned)(r*FAE + ofs)*2u, Vb + (size_t)(k0 + r)*DIMN + ofs);
        }
    };

    #pragma unroll
    for (int u = 0; u < 4; u++) {
        int c = tid + 256*u;
        int r = c >> 3, ofs = (c & 7) * 8;
        *(uint4*)&Qs[r*FAE + ofs] = *(const uint4*)(Qb + (size_t)(q0 + r)*DIMN + ofs);
    }

    loadKV(0, 0);
    asm volatile("cp.async.commit_group;");
    loadKV(1, 64);
    asm volatile("cp.async.commit_group;");

    float o[8][4];
    #pragma unroll
    for (int j = 0; j < 8; j++)
        #pragma unroll
        for (int r = 0; r < 4; r++) o[j][r] = 0.f;
    float m0 = -1e30f, m1 = -1e30f, l0 = 0.f, l1 = 0.f;

    const int NT = SEQL / 64;
    for (int t = 0; t < NT; t++) {
        if (t + 1 < NT) asm volatile("cp.async.wait_group 1;");
        else            asm volatile("cp.async.wait_group 0;");
        __syncthreads();
        if (t + 2 < NT) {
            loadKV((t + 2) % 3, (t + 2) * 64);
            asm volatile("cp.async.commit_group;");
        }

        const unsigned sK = sK0 + (unsigned)(t % 3) * 64*FAE*2u;
        const unsigned sV = sV0 + (unsigned)(t % 3) * 64*FAE*2u;

        float s[8][4];
        #pragma unroll
        for (int j = 0; j < 8; j++)
            #pragma unroll
            for (int r = 0; r < 4; r++) s[j][r] = 0.f;

        #pragma unroll
        for (int kc = 0; kc < 4; kc++) {
            int kk = 16*kc;
            unsigned a0, a1, a2, a3;
            ldmx4(a0, a1, a2, a3, sQ + (unsigned)((wm + lm)*FAE + kk + lh*8)*2u);
            #pragma unroll
            for (int j2 = 0; j2 < 4; j2++) {
                unsigned r0, r1, r2, r3;
                ldmx4(r0, r1, r2, r3,
                      sK + (unsigned)((16*j2 + (lane & 7) + ((lane >> 4) << 3))*FAE
                                       + kk + (((lane >> 3) & 1) << 3))*2u);
                mma16(s[2*j2],     a0, a1, a2, a3, r0, r1);
                mma16(s[2*j2 + 1], a0, a1, a2, a3, r2, r3);
            }
        }

        float tm0 = -1e30f, tm1 = -1e30f;
        #pragma unroll
        for (int j = 0; j < 8; j++) {
            tm0 = fmaxf(tm0, fmaxf(s[j][0], s[j][1]));
            tm1 = fmaxf(tm1, fmaxf(s[j][2], s[j][3]));
        }
        tm0 = fmaxf(tm0, __shfl_xor_sync(0xffffffffu, tm0, 1));
        tm0 = fmaxf(tm0, __shfl_xor_sync(0xffffffffu, tm0, 2));
        tm1 = fmaxf(tm1, __shfl_xor_sync(0xffffffffu, tm1, 1));
        tm1 = fmaxf(tm1, __shfl_xor_sync(0xffffffffu, tm1, 2));
        float mn0 = fmaxf(m0, tm0), mn1 = fmaxf(m1, tm1);
        float c0 = exp2f(m0 - mn0), c1 = exp2f(m1 - mn1);
        float ps0 = 0.f, ps1 = 0.f;
        #pragma unroll
        for (int j = 0; j < 8; j++) {
            s[j][0] = exp2f(s[j][0] - mn0);
            s[j][1] = exp2f(s[j][1] - mn0);
            s[j][2] = exp2f(s[j][2] - mn1);
            s[j][3] = exp2f(s[j][3] - mn1);
            ps0 += s[j][0] + s[j][1];
            ps1 += s[j][2] + s[j][3];
        }
        ps0 += __shfl_xor_sync(0xffffffffu, ps0, 1);
        ps0 += __shfl_xor_sync(0xffffffffu, ps0, 2);
        ps1 += __shfl_xor_sync(0xffffffffu, ps1, 1);
        ps1 += __shfl_xor_sync(0xffffffffu, ps1, 2);
        l0 = l0 * c0 + ps0;  l1 = l1 * c1 + ps1;
        m0 = mn0;            m1 = mn1;
        #pragma unroll
        for (int j = 0; j < 8; j++) {
            o[j][0] *= c0; o[j][1] *= c0; o[j][2] *= c1; o[j][3] *= c1;
        }

        #pragma unroll
        for (int c = 0; c < 4; c++) {
            unsigned pa0 = pack_bf(s[2*c][0],   s[2*c][1]);
            unsigned pa1 = pack_bf(s[2*c][2],   s[2*c][3]);
            unsigned pa2 = pack_bf(s[2*c+1][0], s[2*c+1][1]);
            unsigned pa3 = pack_bf(s[2*c+1][2], s[2*c+1][3]);
            #pragma unroll
            for (int j2 = 0; j2 < 4; j2++) {
                unsigned r0, r1, r2, r3;
                ldmx4t(r0, r1, r2, r3,
                       sV + (unsigned)((16*c + lm)*FAE + 16*j2 + lh*8)*2u);
                mma16(o[2*j2],     pa0, pa1, pa2, pa3, r0, r1);
                mma16(o[2*j2 + 1], pa0, pa1, pa2, pa3, r2, r3);
            }
        }
    }

    float inv0 = 1.f / l0, inv1 = 1.f / l1;
    #pragma unroll
    for (int j = 0; j < 8; j++) {
        int col = 8*j + 2*t4;
        *(unsigned*)(Ob + (size_t)(q0 + wm + g    )*DIMN + col) = pack_bf(o[j][0]*inv0, o[j][1]*inv0);
        *(unsigned*)(Ob + (size_t)(q0 + wm + g + 8)*DIMN + col) = pack_bf(o[j][2]*inv1, o[j][3]*inv1);
    }
}

__global__ __launch_bounds__(256) void residual_norm(const float* __restrict__ xb,
                                                     const bf16* __restrict__ br,
                                                     const float* __restrict__ alpha,
                                                     float* __restrict__ out,
                                                     bf16* __restrict__ xp) {
    int t = blockIdx.x;
    int tid = threadIdx.x;
    const float* xr = xb + (size_t)t * DIMN;
    const bf16*  rr = br + (size_t)t * DIMN;
    float xv[4], bv[4];
    float ssx = 0.f, ssb = 0.f;
    #pragma unroll
    for (int u = 0; u < 2; u++) {
        int d = tid*2 + u * 512;
        float2 xx = *(const float2*)(xr + d);
        float2 bb = unpack_bf(*(const unsigned*)(rr + d));
        xv[2*u] = xx.x; xv[2*u+1] = xx.y;
        bv[2*u] = bb.x; bv[2*u+1] = bb.y;
        ssx += xx.x*xx.x + xx.y*xx.y;
        ssb += bb.x*bb.x + bb.y*bb.y;
    }
    ssx = blockSum256(ssx);
    ssb = blockSum256(ssb);
    float rx = 1.f / fmaxf(sqrtf(ssx), 1e-12f);
    float rb = 1.f / fmaxf(sqrtf(ssb), 1e-12f);
    float yv[4]; float ssy = 0.f;
    #pragma unroll
    for (int u = 0; u < 4; u++) {
        int d = tid*2 + (u >> 1) * 512 + (u & 1);
        float hh = xv[u] * rx;
        float ha = bv[u] * rb;
        float lr = fabsf(alpha[d] * 1.6f);
        float y = hh + lr * (ha - hh);
        yv[u] = y; ssy += y * y;
    }
    ssy = blockSum256(ssy);
    float ry = 1.f / fmaxf(sqrtf(ssy), 1e-12f);
    int b = t >> 11, se = t & 2047;
    int ip = se >> 4, p = se & 15;
    #pragma unroll
    for (int u = 0; u < 4; u++) {
        int d = tid*2 + (u >> 1) * 512 + (u & 1);
        float y = yv[u] * ry;
        out[(size_t)t * DIMN + d] = y;
        if (xp) {
            int jj = d >> 4, qq = d & 15;
            xp[((size_t)b*8192 + ip*64 + jj)*256 + p*16 + qq] = __float2bfloat16_rn(y);
        }
    }
}

extern "C" void kernel_launch(void* const* d_in, const int* in_sizes, int n_in,
                              void* d_out, int out_size) {
    const float* x      = (const float*)d_in[0];
    const float* fcos   = (const float*)d_in[1];
    const float* fsin   = (const float*)d_in[2];
    const float* adafm  = (const float*)d_in[3];
    const float* wq     = (const float*)d_in[4];
    const float* wk     = (const float*)d_in[5];
    const float* wv     = (const float*)d_in[6];
    const float* wo     = (const float*)d_in[7];
    const float* sqk    = (const float*)d_in[8];
    const float* w1     = (const float*)d_in[9];
    const float* w2     = (const float*)d_in[10];
    const float* w3     = (const float*)d_in[11];
    const float* su     = (const float*)d_in[12];
    const float* sv     = (const float*)d_in[13];
    const float* pw     = (const float*)d_in[14];
    const float* pb     = (const float*)d_in[15];
    const float* aalpha = (const float*)d_in[16];
    const float* malpha = (const float*)d_in[17];
    float* out = (float*)d_out;

    float *ptp, *pf0;
    bf16 *pbgm, *pbgf, *pbxa, *pbq, *pbk, *pbv, *pbao, *pbwo, *pbxp;
    unsigned char *pxm8;
    cudaGetSymbolAddress((void**)&ptp, d_tp);
    cudaGetSymbolAddress((void**)&pf0, d_f0);
    cudaGetSymbolAddress((void**)&pbgm, b_gm);
    cudaGetSymbolAddress((void**)&pbgf, b_gf);
    cudaGetSymbolAddress((void**)&pbxa, b_xa);
    cudaGetSymbolAddress((void**)&pbq,  b_q);
    cudaGetSymbolAddress((void**)&pbk,  b_k);
    cudaGetSymbolAddress((void**)&pbv,  b_v);
    cudaGetSymbolAddress((void**)&pbao, b_ao);
    cudaGetSymbolAddress((void**)&pbwo, b_wo);
    cudaGetSymbolAddress((void**)&pbxp, b_xp);
    cudaGetSymbolAddress((void**)&pxm8, b_xm8);

    cudaFuncSetAttribute(gemm_bf16o, cudaFuncAttributeMaxDynamicSharedMemorySize, GEMM_SMEM);
    cudaFuncSetAttribute(gemm_qkv, cudaFuncAttributeMaxDynamicSharedMemorySize, GEMM_SMEM);
    cudaFuncSetAttribute(adafm_gemm, cudaFuncAttributeMaxDynamicSharedMemorySize, GEMM_SMEM);
    cudaFuncSetAttribute(gemm_ffn13f8, cudaFuncAttributeMaxDynamicSharedMemorySize, FFN8_SMEM);
    cudaFuncSetAttribute(gemm_w2f8, cudaFuncAttributeMaxDynamicSharedMemorySize, W2F8_SMEM);
    cudaFuncSetAttribute(flash_attn, cudaFuncAttributeMaxDynamicSharedMemorySize, FLASH_SMEM);

    // 0) all weight conversions in one launch
    cvt_mega<<<9472, 256>>>(wq, wk, wv, wo, w1, w3, w2);

    // 1) time-modulation (split-K proj_t; reduction folded into make_g)
    proj_t_part<<<dim3(BATCH, 16, 8), 256>>>(adafm, pw, ptp);
    make_g_kernel<<<dim3(4, 32), 256>>>(ptp, pb);

    // 2) attention branch
    patchify<<<2048, 256>>>(x);
    adafm_gemm<<<dim3(1, 64, 2), 256, GEMM_SMEM>>>(pbgm, pbxa, (unsigned char*)0);
    gemm_qkv<<<dim3(12, 32), 256, GEMM_SMEM>>>(pbxa, fcos, fsin, sqk);
    flash_attn<<<dim3(SEQL/128, NHEAD, BATCH), 256, FLASH_SMEM>>>(pbq, pbk, pbv, pbao);
    gemm_bf16o<<<dim3(DIMN/256, TOK/128), 256, GEMM_SMEM>>>(pbao, pbwo, pbq, TOK, DIMN, DIMN);
    residual_norm<<<TOK, 256>>>(x, pbq, aalpha, pf0, pbxp);

    // 3) FFN branch (fp8)
    adafm_gemm<<<dim3(1, 64, 2), 256, GEMM_SMEM>>>(pbgf, (bf16*)0, pxm8);
    gemm_ffn13f8<<<dim3(HIDDEN/128, TOK/128), 256, FFN8_SMEM>>>(su, sv);
    gemm_w2f8<<<dim3(DIMN/256, TOK/128), 256, W2F8_SMEM>>>(pbk);
    residual_norm<<<TOK, 256>>>(pf0, pbk, malpha, out, (bf16*)0);
}